// round 4
// baseline (speedup 1.0000x reference)
#include <cuda_runtime.h>
#include <cuda_bf16.h>
#include <cstdint>
#include <cstddef>

// Problem constants
// B=4, T=2048, C=1024, H=16, D=64
#define NB 4
#define NT 2048
#define NC 1024
#define NH 16
#define ND 64

// Head-major scratch [B,H,T,D] for q,k,v; attention output in [B,T,C] for proj GEMM.
__device__ float g_q[(size_t)NB * NH * NT * ND];
__device__ float g_k[(size_t)NB * NH * NT * ND];
__device__ float g_v[(size_t)NB * NH * NT * ND];
__device__ float g_ao[(size_t)NB * NT * NC];

__device__ __forceinline__ float ftf32(float x) {
    unsigned u;
    asm("cvt.rna.tf32.f32 %0, %1;" : "=r"(u) : "f"(x));
    return __uint_as_float(u);
}

__device__ __forceinline__ void mma8(float* c, const unsigned* a, const unsigned* b) {
    asm volatile(
        "mma.sync.aligned.m16n8k8.row.col.f32.tf32.tf32.f32 "
        "{%0,%1,%2,%3}, {%4,%5,%6,%7}, {%8,%9}, {%0,%1,%2,%3};\n"
        : "+f"(c[0]), "+f"(c[1]), "+f"(c[2]), "+f"(c[3])
        : "r"(a[0]), "r"(a[1]), "r"(a[2]), "r"(a[3]), "r"(b[0]), "r"(b[1]));
}

// Scatter epilogue for the QKV GEMM: col in [0,3072) -> (s, h, d); row -> (b, t).
// q is pre-scaled by 1/sqrt(D) = 0.125.
__device__ __forceinline__ void scatter_qkv(int gm, int gc, float v) {
    int s = gc >> 10;
    int rem = gc & 1023;
    int h = rem >> 6;
    int d = rem & 63;
    int b = gm >> 11;
    int t = gm & 2047;
    size_t idx = (((size_t)(b * NH + h)) * NT + t) * ND + d;
    if (s == 0)      g_q[idx] = v * 0.125f;
    else if (s == 1) g_k[idx] = v;
    else             g_v[idx] = v;
}

// ---------------------------------------------------------------------------
// TF32 GEMM: C[M x N] = A[M x K] * B[K x N], both row-major fp32.
// Block tile 128x128, K-tile 16, double-buffered smem.
// 4 warps (2x2 warp grid), warp tile 64x64 -- big warp tiles cut smem
// fragment traffic to 48KB per K-tile (384 cyc) vs 512-cyc tensor floor.
// EPI: 0 = plain store to Cout, 1 = scatter into g_q/g_k/g_v.
// ASRC: 0 = A param, 1 = A is g_ao (attention output).
// ---------------------------------------------------------------------------
template <int N, int K, int EPI, int ASRC>
__global__ __launch_bounds__(128, 2)
void gemm_tf32(const float* __restrict__ A, const float* __restrict__ Bm,
               float* __restrict__ Cout) {
    __shared__ float As[2][128][20];   // pitch 20: frag reads conflict-free
    __shared__ float Bs[2][16][136];   // pitch 136: frag reads conflict-free

    const int tid = threadIdx.x;
    const int lane = tid & 31, warp = tid >> 5;
    const int wm = warp & 1, wn = warp >> 1;        // 2x2 warp grid
    const int quad = lane >> 2, qid = lane & 3;
    const int bm = blockIdx.y * 128, bn = blockIdx.x * 128;

    const float* Ap = ASRC ? (const float*)g_ao : A;

    // gmem load mapping (128 threads)
    // A: thread = one row (0..127), 16 floats along k (4 x float4)
    // B: row = tid>>3 (0..15), cols (tid&7)*16 .. +15 (4 x float4)
    const int brow = tid >> 3;
    const int bcol = (tid & 7) * 16;

    float acc[4][8][4];
#pragma unroll
    for (int i = 0; i < 4; i++)
#pragma unroll
        for (int j = 0; j < 8; j++)
#pragma unroll
            for (int k = 0; k < 4; k++) acc[i][j][k] = 0.f;

    float4 ra[4], rb[4];
    const int nk = K / 16;

#define LOADG(kt_)                                                             \
    {                                                                          \
        const float* ap_ = Ap + (size_t)(bm + tid) * K + (kt_) * 16;           \
        ra[0] = *(const float4*)ap_;                                           \
        ra[1] = *(const float4*)(ap_ + 4);                                     \
        ra[2] = *(const float4*)(ap_ + 8);                                     \
        ra[3] = *(const float4*)(ap_ + 12);                                    \
        const float* bp_ = Bm + (size_t)((kt_) * 16 + brow) * N + bn + bcol;   \
        rb[0] = *(const float4*)bp_;                                           \
        rb[1] = *(const float4*)(bp_ + 4);                                     \
        rb[2] = *(const float4*)(bp_ + 8);                                     \
        rb[3] = *(const float4*)(bp_ + 12);                                    \
    }

#define STORES(bb_)                                                            \
    {                                                                          \
        float* a0_ = &As[bb_][tid][0];                                         \
        a0_[0]  = ftf32(ra[0].x); a0_[1]  = ftf32(ra[0].y);                    \
        a0_[2]  = ftf32(ra[0].z); a0_[3]  = ftf32(ra[0].w);                    \
        a0_[4]  = ftf32(ra[1].x); a0_[5]  = ftf32(ra[1].y);                    \
        a0_[6]  = ftf32(ra[1].z); a0_[7]  = ftf32(ra[1].w);                    \
        a0_[8]  = ftf32(ra[2].x); a0_[9]  = ftf32(ra[2].y);                    \
        a0_[10] = ftf32(ra[2].z); a0_[11] = ftf32(ra[2].w);                    \
        a0_[12] = ftf32(ra[3].x); a0_[13] = ftf32(ra[3].y);                    \
        a0_[14] = ftf32(ra[3].z); a0_[15] = ftf32(ra[3].w);                    \
        float* b0_ = &Bs[bb_][brow][bcol];                                     \
        b0_[0]  = ftf32(rb[0].x); b0_[1]  = ftf32(rb[0].y);                    \
        b0_[2]  = ftf32(rb[0].z); b0_[3]  = ftf32(rb[0].w);                    \
        b0_[4]  = ftf32(rb[1].x); b0_[5]  = ftf32(rb[1].y);                    \
        b0_[6]  = ftf32(rb[1].z); b0_[7]  = ftf32(rb[1].w);                    \
        b0_[8]  = ftf32(rb[2].x); b0_[9]  = ftf32(rb[2].y);                    \
        b0_[10] = ftf32(rb[2].z); b0_[11] = ftf32(rb[2].w);                    \
        b0_[12] = ftf32(rb[3].x); b0_[13] = ftf32(rb[3].y);                    \
        b0_[14] = ftf32(rb[3].z); b0_[15] = ftf32(rb[3].w);                    \
    }

    LOADG(0);
    STORES(0);
    __syncthreads();

    for (int kt = 0; kt < nk; kt++) {
        const int bb = kt & 1;
        const bool more = (kt + 1 < nk);
        if (more) LOADG(kt + 1);

#pragma unroll
        for (int kb = 0; kb < 16; kb += 8) {
            unsigned bf[8][2];
#pragma unroll
            for (int nt = 0; nt < 8; nt++) {
                int cn = wn * 64 + nt * 8 + quad;
                bf[nt][0] = __float_as_uint(Bs[bb][kb + qid][cn]);
                bf[nt][1] = __float_as_uint(Bs[bb][kb + qid + 4][cn]);
            }
#pragma unroll
            for (int mt = 0; mt < 4; mt++) {
                unsigned af[4];
                int r = wm * 64 + mt * 16 + quad;
                af[0] = __float_as_uint(As[bb][r][kb + qid]);
                af[1] = __float_as_uint(As[bb][r + 8][kb + qid]);
                af[2] = __float_as_uint(As[bb][r][kb + qid + 4]);
                af[3] = __float_as_uint(As[bb][r + 8][kb + qid + 4]);
#pragma unroll
                for (int nt = 0; nt < 8; nt++)
                    mma8(acc[mt][nt], af, bf[nt]);
            }
        }

        if (more) STORES(bb ^ 1);
        __syncthreads();
    }
#undef LOADG
#undef STORES

    // Epilogue
#pragma unroll
    for (int mt = 0; mt < 4; mt++) {
        int r0 = bm + wm * 64 + mt * 16 + quad;
#pragma unroll
        for (int nt = 0; nt < 8; nt++) {
            int c0 = bn + wn * 64 + nt * 8 + 2 * qid;
            float* cc = acc[mt][nt];
            if constexpr (EPI == 0) {
                Cout[(size_t)r0 * N + c0] = cc[0];
                Cout[(size_t)r0 * N + c0 + 1] = cc[1];
                Cout[(size_t)(r0 + 8) * N + c0] = cc[2];
                Cout[(size_t)(r0 + 8) * N + c0 + 1] = cc[3];
            } else {
                scatter_qkv(r0, c0, cc[0]);
                scatter_qkv(r0, c0 + 1, cc[1]);
                scatter_qkv(r0 + 8, c0, cc[2]);
                scatter_qkv(r0 + 8, c0 + 1, cc[3]);
            }
        }
    }
}

// ---------------------------------------------------------------------------
// Flash attention (causal, online softmax) on the tensor pipe (tf32 mma).
// Block: 128 threads (4 warps). q-tile 128 rows (32 per warp: mt=2),
// k-tile 64 keys. Grid: (T/128 = 16, B*H = 64). Causal: kt <= 2*qt+1 tiles.
// Bigger per-warp q-tile amortizes K/V B-fragment smem reads (the R2
// bottleneck) over 2x the output rows -> tensor-bound.
//
// S = Q K^T via mma.m16n8k8 with Q split into tf32 (hi, lo) pair.
// Softmax in MMA accumulator layout; row stats via shfl over quad lanes.
// P goes through smem (per-warp private rows -> __syncwarp only).
// ---------------------------------------------------------------------------
__global__ __launch_bounds__(128)
void attn_mma() {
    extern __shared__ float sm[];
    float (*Qh)[68] = (float(*)[68])(sm);              // 128x68
    float (*Ql)[68] = (float(*)[68])(sm + 8704);       // 128x68
    float (*Ks)[68] = (float(*)[68])(sm + 17408);      // 64x68
    float (*Vs)[72] = (float(*)[72])(sm + 21760);      // 64x72
    float (*Ps)[68] = (float(*)[68])(sm + 26368);      // 128x68  (total 140288 B)

    const int qt = blockIdx.x;      // q tile (0..15), 128 rows each
    const int bh = blockIdx.y;      // b*H + h
    const int b = bh >> 4, h = bh & 15;

    const int tid = threadIdx.x;
    const int lane = tid & 31, warp = tid >> 5;
    const int g = lane >> 2, q4 = lane & 3;

    const float* Qg = g_q + ((size_t)bh * NT + (size_t)qt * 128) * ND;
    const float* Kg = g_k + (size_t)bh * NT * ND;
    const float* Vg = g_v + (size_t)bh * NT * ND;

    // Load Q tile (128x64), split into tf32 hi/lo
#pragma unroll
    for (int i = 0; i < 16; i++) {
        int idx = tid + i * 128;
        int r = idx >> 4, c = (idx & 15) * 4;
        float4 qv = *(const float4*)&Qg[r * 64 + c];
        float h0 = ftf32(qv.x), h1 = ftf32(qv.y), h2 = ftf32(qv.z), h3 = ftf32(qv.w);
        Qh[r][c + 0] = h0; Qh[r][c + 1] = h1; Qh[r][c + 2] = h2; Qh[r][c + 3] = h3;
        Ql[r][c + 0] = ftf32(qv.x - h0);
        Ql[r][c + 1] = ftf32(qv.y - h1);
        Ql[r][c + 2] = ftf32(qv.z - h2);
        Ql[r][c + 3] = ftf32(qv.w - h3);
    }

    // per-warp rows: warp*32 + mt*16 + g (+8)
    int row_lo[2], row_hi[2], grow_lo[2], grow_hi[2];
#pragma unroll
    for (int mt = 0; mt < 2; mt++) {
        row_lo[mt] = warp * 32 + mt * 16 + g;
        row_hi[mt] = row_lo[mt] + 8;
        grow_lo[mt] = qt * 128 + row_lo[mt];
        grow_hi[mt] = grow_lo[mt] + 8;
    }

    float m_[2][2] = {{-1e30f, -1e30f}, {-1e30f, -1e30f}};
    float l_[2][2] = {{0.f, 0.f}, {0.f, 0.f}};
    float oacc[2][8][4];
#pragma unroll
    for (int mt = 0; mt < 2; mt++)
#pragma unroll
        for (int nt = 0; nt < 8; nt++)
#pragma unroll
            for (int j = 0; j < 4; j++) oacc[mt][nt][j] = 0.f;

    const int nkt = 2 * qt + 2;     // k-tiles of 64 up to (and incl.) diagonal
    for (int kt = 0; kt < nkt; kt++) {
        __syncthreads();   // all warps done with previous Ks/Vs (and Q ready on kt=0)
        const float* kp = Kg + (size_t)kt * 64 * 64;
        const float* vp = Vg + (size_t)kt * 64 * 64;
#pragma unroll
        for (int i = 0; i < 8; i++) {
            int idx = tid + i * 128;
            int r = idx >> 4, c = (idx & 15) * 4;
            float4 kv = *(const float4*)&kp[r * 64 + c];
            Ks[r][c + 0] = ftf32(kv.x); Ks[r][c + 1] = ftf32(kv.y);
            Ks[r][c + 2] = ftf32(kv.z); Ks[r][c + 3] = ftf32(kv.w);
            float4 vv = *(const float4*)&vp[r * 64 + c];
            Vs[r][c + 0] = ftf32(vv.x); Vs[r][c + 1] = ftf32(vv.y);
            Vs[r][c + 2] = ftf32(vv.z); Vs[r][c + 3] = ftf32(vv.w);
        }
        __syncthreads();

        // ---- S = Q K^T (split-precision: hi + lo) ----
        float sacc[2][8][4];
#pragma unroll
        for (int mt = 0; mt < 2; mt++)
#pragma unroll
            for (int nt = 0; nt < 8; nt++)
#pragma unroll
                for (int j = 0; j < 4; j++) sacc[mt][nt][j] = 0.f;

#pragma unroll
        for (int kb = 0; kb < 64; kb += 8) {
            unsigned bf[8][2];
#pragma unroll
            for (int nt = 0; nt < 8; nt++) {
                bf[nt][0] = __float_as_uint(Ks[nt * 8 + g][kb + q4]);
                bf[nt][1] = __float_as_uint(Ks[nt * 8 + g][kb + q4 + 4]);
            }
#pragma unroll
            for (int mt = 0; mt < 2; mt++) {
                unsigned ah[4], al[4];
                ah[0] = __float_as_uint(Qh[row_lo[mt]][kb + q4]);
                ah[1] = __float_as_uint(Qh[row_hi[mt]][kb + q4]);
                ah[2] = __float_as_uint(Qh[row_lo[mt]][kb + q4 + 4]);
                ah[3] = __float_as_uint(Qh[row_hi[mt]][kb + q4 + 4]);
                al[0] = __float_as_uint(Ql[row_lo[mt]][kb + q4]);
                al[1] = __float_as_uint(Ql[row_hi[mt]][kb + q4]);
                al[2] = __float_as_uint(Ql[row_lo[mt]][kb + q4 + 4]);
                al[3] = __float_as_uint(Ql[row_hi[mt]][kb + q4 + 4]);
#pragma unroll
                for (int nt = 0; nt < 8; nt++) {
                    mma8(sacc[mt][nt], ah, bf[nt]);
                    mma8(sacc[mt][nt], al, bf[nt]);
                }
            }
        }

        // ---- causal mask (only the two diagonal-straddling tiles) ----
        if (kt >= 2 * qt) {
#pragma unroll
            for (int mt = 0; mt < 2; mt++)
#pragma unroll
                for (int nt = 0; nt < 8; nt++) {
                    int c0 = kt * 64 + nt * 8 + 2 * q4;
                    if (c0 > grow_lo[mt])     sacc[mt][nt][0] = -1e30f;
                    if (c0 + 1 > grow_lo[mt]) sacc[mt][nt][1] = -1e30f;
                    if (c0 > grow_hi[mt])     sacc[mt][nt][2] = -1e30f;
                    if (c0 + 1 > grow_hi[mt]) sacc[mt][nt][3] = -1e30f;
                }
        }

        // ---- online softmax (acc layout; stats over quad lanes) ----
#pragma unroll
        for (int mt = 0; mt < 2; mt++) {
#pragma unroll
            for (int half = 0; half < 2; half++) {
                const int j0 = half * 2;
                float rmax = -1e30f;
#pragma unroll
                for (int nt = 0; nt < 8; nt++)
                    rmax = fmaxf(rmax, fmaxf(sacc[mt][nt][j0], sacc[mt][nt][j0 + 1]));
                rmax = fmaxf(rmax, __shfl_xor_sync(0xffffffffu, rmax, 1));
                rmax = fmaxf(rmax, __shfl_xor_sync(0xffffffffu, rmax, 2));
                float mnew = fmaxf(m_[mt][half], rmax);
                float alpha = __expf(m_[mt][half] - mnew);
                float rs = 0.f;
#pragma unroll
                for (int nt = 0; nt < 8; nt++) {
                    float p0 = __expf(sacc[mt][nt][j0] - mnew);
                    float p1 = __expf(sacc[mt][nt][j0 + 1] - mnew);
                    rs += p0 + p1;
                    sacc[mt][nt][j0] = p0; sacc[mt][nt][j0 + 1] = p1;
                }
                rs += __shfl_xor_sync(0xffffffffu, rs, 1);
                rs += __shfl_xor_sync(0xffffffffu, rs, 2);
                l_[mt][half] = l_[mt][half] * alpha + rs;
                m_[mt][half] = mnew;
#pragma unroll
                for (int nt = 0; nt < 8; nt++) {
                    oacc[mt][nt][j0] *= alpha;
                    oacc[mt][nt][j0 + 1] *= alpha;
                }
            }
        }

        // ---- P: acc layout -> smem -> A-frag layout (warp-private rows) ----
#pragma unroll
        for (int mt = 0; mt < 2; mt++)
#pragma unroll
            for (int nt = 0; nt < 8; nt++) {
                float2 plo = make_float2(ftf32(sacc[mt][nt][0]), ftf32(sacc[mt][nt][1]));
                float2 phi = make_float2(ftf32(sacc[mt][nt][2]), ftf32(sacc[mt][nt][3]));
                *(float2*)&Ps[row_lo[mt]][nt * 8 + 2 * q4] = plo;
                *(float2*)&Ps[row_hi[mt]][nt * 8 + 2 * q4] = phi;
            }
        __syncwarp();

        // ---- O += P V ----
#pragma unroll
        for (int kb = 0; kb < 64; kb += 8) {
            unsigned bf[8][2];
#pragma unroll
            for (int nt = 0; nt < 8; nt++) {
                bf[nt][0] = __float_as_uint(Vs[kb + q4][nt * 8 + g]);
                bf[nt][1] = __float_as_uint(Vs[kb + q4 + 4][nt * 8 + g]);
            }
#pragma unroll
            for (int mt = 0; mt < 2; mt++) {
                unsigned af[4];
                af[0] = __float_as_uint(Ps[row_lo[mt]][kb + q4]);
                af[1] = __float_as_uint(Ps[row_hi[mt]][kb + q4]);
                af[2] = __float_as_uint(Ps[row_lo[mt]][kb + q4 + 4]);
                af[3] = __float_as_uint(Ps[row_hi[mt]][kb + q4 + 4]);
#pragma unroll
                for (int nt = 0; nt < 8; nt++)
                    mma8(oacc[mt][nt], af, bf[nt]);
            }
        }
    }

    // ---- normalize and write to [B, T, C] ----
#pragma unroll
    for (int mt = 0; mt < 2; mt++) {
        float inv0 = 1.f / l_[mt][0], inv1 = 1.f / l_[mt][1];
        float* op_lo = g_ao + ((size_t)(b * NT + grow_lo[mt])) * NC + h * ND;
        float* op_hi = g_ao + ((size_t)(b * NT + grow_hi[mt])) * NC + h * ND;
#pragma unroll
        for (int nt = 0; nt < 8; nt++) {
            int c0 = nt * 8 + 2 * q4;
            *(float2*)&op_lo[c0] =
                make_float2(oacc[mt][nt][0] * inv0, oacc[mt][nt][1] * inv0);
            *(float2*)&op_hi[c0] =
                make_float2(oacc[mt][nt][2] * inv1, oacc[mt][nt][3] * inv1);
        }
    }
}

// ---------------------------------------------------------------------------
extern "C" void kernel_launch(void* const* d_in, const int* in_sizes, int n_in,
                              void* d_out, int out_size) {
    (void)in_sizes; (void)n_in; (void)out_size;
    const float* x      = (const float*)d_in[0];  // [B,T,C] = [8192,1024]
    const float* w_qkv  = (const float*)d_in[1];  // [1024,3072]
    const float* w_proj = (const float*)d_in[2];  // [1024,1024]
    float* out = (float*)d_out;                   // [8192,1024]

    const int attn_smem = 140288;
    cudaFuncSetAttribute(attn_mma, cudaFuncAttributeMaxDynamicSharedMemorySize, attn_smem);

    // 1) qkv = x @ w_qkv, scattered into head-major q/k/v (q pre-scaled)
    gemm_tf32<3072, 1024, 1, 0><<<dim3(24, 64), 128>>>(x, w_qkv, nullptr);
    // 2) causal flash attention (tensor-pipe tf32) -> g_ao [B,T,C]
    attn_mma<<<dim3(16, 64), 128, attn_smem>>>();
    // 3) out = attn_out @ w_proj
    gemm_tf32<1024, 1024, 0, 1><<<dim3(8, 64), 128>>>(nullptr, w_proj, out);
}